// round 16
// baseline (speedup 1.0000x reference)
#include <cuda_runtime.h>
#include <cuda_fp16.h>
#include <cstdint>

#define NSTREAMS 2
#define NB 8
#define C_IN 256
#define HID 128
#define NTOK 2304
#define QSCL 0.09016844005f   // 256^-0.5 * log2(e), folded into q (via wh rows o<128)

// ---------------- scratch (device globals; no allocs allowed) ----------------
// g_qh/g_kh rows use a PERMUTED d-order; g_vh rows use the same permutation
// on n within each 128-token block:  val(16k+8h+2j+b) stored at byte 32k+8j+4h+2b.
__device__ __half   g_qh[NSTREAMS][NB][NTOK][HID];
__device__ __half   g_kh[NSTREAMS][NB][NTOK][HID];
__device__ __half   g_vh[NSTREAMS][NB][HID][NTOK];
__device__ uint32_t g_w2[NSTREAMS][C_IN][HID / 2];  // W_eff [o][c2] half2 (c even lo)
__device__ uint32_t g_wh[NSTREAMS][384][C_IN / 2];  // embed W fp16 pairs [o][c2]

// ---------------- helpers ----------------
__device__ __forceinline__ float ex2f(float x) {
    float y; asm("ex2.approx.ftz.f32 %0, %1;" : "=f"(y) : "f"(x)); return y;
}
__device__ __forceinline__ uint32_t packh(float lo, float hi) {
    uint32_t d; asm("cvt.rn.f16x2.f32 %0, %1, %2;" : "=r"(d) : "f"(hi), "f"(lo));
    return d;
}
__device__ __forceinline__ void mma16(float c[4], const uint32_t a[4],
                                      uint32_t b0, uint32_t b1) {
    asm volatile(
        "mma.sync.aligned.m16n8k16.row.col.f32.f16.f16.f32 "
        "{%0,%1,%2,%3}, {%4,%5,%6,%7}, {%8,%9}, {%0,%1,%2,%3};"
        : "+f"(c[0]), "+f"(c[1]), "+f"(c[2]), "+f"(c[3])
        : "r"(a[0]), "r"(a[1]), "r"(a[2]), "r"(a[3]), "r"(b0), "r"(b1));
}
__device__ __forceinline__ uint32_t smem_u32(const void* p) {
    uint32_t a;
    asm("{ .reg .u64 t; cvta.to.shared.u64 t, %1; cvt.u32.u64 %0, t; }" : "=r"(a) : "l"(p));
    return a;
}
// in-row permutation: value index v (0..127) -> byte offset (0..255)
__device__ __forceinline__ int permb(int v) {
    int ks = v >> 4, r = v & 15;
    return 32 * ks + 8 * ((r >> 1) & 3) + 4 * (r >> 3) + 2 * (v & 1);
}
#define CP16(dst, src) asm volatile("cp.async.cg.shared.global [%0], [%1], 16;" :: "r"(dst), "l"(src))
#define CP_COMMIT()    asm volatile("cp.async.commit_group;" ::: "memory")
#define CP_WAIT1()     asm volatile("cp.async.wait_group 1;" ::: "memory")
#define CP_WAIT0()     asm volatile("cp.async.wait_group 0;" ::: "memory")

// ---------------- pre-convert embed weight to fp16 pairs (QSCL folded for q) ----------------
__global__ void wh_kernel(const float* __restrict__ w0, const float* __restrict__ w1) {
    int o = blockIdx.x;
    int s = blockIdx.y;
    const float* w = (s == 0 ? w0 : w1) + (size_t)o * C_IN;
    float scl = (o < HID) ? QSCL : 1.0f;
    int c2 = threadIdx.x;
    g_wh[s][o][c2] = packh(w[2 * c2] * scl, w[2 * c2 + 1] * scl);
}

// =======================================================================
// embed (fp16 mma): one CTA computes q,k,v for a 64-token m-tile.
// Outputs written in the attn-fragment permuted order (see permb).
// =======================================================================
__global__ void __launch_bounds__(256, 2) embed_kernel(
        const float* __restrict__ x0, const float* __restrict__ x1,
        const float* __restrict__ b0_, const float* __restrict__ b1_) {
    extern __shared__ char esm[];
    uint32_t* sX = (uint32_t*)esm;          // [32 c2][72 pad] half2 words
    char* wsm = esm + 9216;                 // 3 oy x 16384 B, chunk-XOR swizzled
    float* sT = (float*)(esm + 9216);       // [128 d][66 m] transpose overlay

    int z = blockIdx.y;
    int s = z >> 3, b = z & 7;
    const float* x = (s == 0 ? x0 : x1) + (size_t)b * C_IN * NTOK;
    const float* bias = (s == 0 ? b0_ : b1_);
    const uint32_t* wh = &g_wh[s][0][0];
    int m0 = blockIdx.x * 64;
    int tid = threadIdx.x;
    int l = tid & 31, wq = tid >> 5;
    int g = l >> 2, j = l & 3;
    uint32_t sb = smem_u32(esm);

    float acc[3][8][4] = {};

    for (int c = 0; c < 4; c++) {
        int k0 = 64 * c;
#pragma unroll
        for (int u = 0; u < 12; u++) {
            int idx = tid + 256 * u;
            int oyi = idx >> 10, rem = idx & 1023;
            int row = rem >> 3, ch = rem & 7;
            uint32_t dst = sb + 9216u + (uint32_t)oyi * 16384u
                         + (uint32_t)row * 128u + (uint32_t)((ch ^ (row & 7)) << 4);
            const char* src = (const char*)(wh + (size_t)(oyi * 128 + row) * 128
                                            + (k0 >> 1) + ch * 4);
            CP16(dst, src);
        }
        CP_COMMIT();
#pragma unroll
        for (int u = 0; u < 2; u++) {
            int idx = tid + 256 * u;
            int k2 = idx >> 4, m4 = idx & 15;
            const float* xa = x + (size_t)(k0 + 2 * k2) * NTOK + m0 + 4 * m4;
            float4 fa = *(const float4*)xa;
            float4 fb = *(const float4*)(xa + NTOK);
            uint4 p;
            p.x = packh(fa.x, fb.x); p.y = packh(fa.y, fb.y);
            p.z = packh(fa.z, fb.z); p.w = packh(fa.w, fb.w);
            *(uint4*)(sX + k2 * 72 + 4 * m4) = p;
        }
        CP_WAIT0();
        __syncthreads();
#pragma unroll
        for (int oy = 0; oy < 3; oy++) {
            const char* wrow0 = wsm + oy * 16384 + (16 * wq + g) * 128;
            const char* wrow1 = wrow0 + 8 * 128;
#pragma unroll
            for (int ks = 0; ks < 4; ks++) {
                int e0 = ((2 * ks) ^ g) * 16 + 4 * j;
                int e1 = ((2 * ks + 1) ^ g) * 16 + 4 * j;
                uint32_t a[4];
                a[0] = *(const uint32_t*)(wrow0 + e0);
                a[1] = *(const uint32_t*)(wrow1 + e0);
                a[2] = *(const uint32_t*)(wrow0 + e1);
                a[3] = *(const uint32_t*)(wrow1 + e1);
                const uint32_t* xb0 = sX + (8 * ks + j) * 72 + g;
                const uint32_t* xb1 = sX + (8 * ks + 4 + j) * 72 + g;
#pragma unroll
                for (int nt = 0; nt < 8; nt++)
                    mma16(acc[oy][nt], a, xb0[8 * nt], xb1[8 * nt]);
            }
        }
        __syncthreads();
    }

    {   // v epilogue: channel-major rows, PERMUTED n within 128-blocks
        int d0 = 16 * wq + g, d1 = d0 + 8;
        float bv0 = bias[256 + d0], bv1 = bias[256 + d1];
        char* v0 = (char*)&g_vh[s][b][d0][0];
        char* v1 = (char*)&g_vh[s][b][d1][0];
#pragma unroll
        for (int nt = 0; nt < 8; nt++) {
            int m = m0 + 8 * nt + 2 * j;
            int off = (m & ~127) * 2 + permb(m & 127);
            *(__half2*)(v0 + off) = __floats2half2_rn(acc[2][nt][0] + bv0, acc[2][nt][1] + bv0);
            *(__half2*)(v1 + off) = __floats2half2_rn(acc[2][nt][2] + bv1, acc[2][nt][3] + bv1);
        }
    }
#pragma unroll
    for (int oy = 0; oy < 2; oy++) {   // q/k transpose epilogue, PERMUTED d
        __syncthreads();
        int d0 = 16 * wq + g, d1 = d0 + 8;
#pragma unroll
        for (int nt = 0; nt < 8; nt++) {
            int m = 8 * nt + 2 * j;
            *(float2*)(sT + d0 * 66 + m) = make_float2(acc[oy][nt][0], acc[oy][nt][1]);
            *(float2*)(sT + d1 * 66 + m) = make_float2(acc[oy][nt][2], acc[oy][nt][3]);
        }
        __syncthreads();
        float bscl = (oy == 0) ? QSCL : 1.0f;
        __half* base = (oy == 0) ? &g_qh[s][b][0][0] : &g_kh[s][b][0][0];
        float bv[4];
        int pb[4];
#pragma unroll
        for (int k = 0; k < 4; k++) {
            bv[k] = bias[oy * 128 + l + 32 * k] * bscl;
            pb[k] = permb(l + 32 * k);
        }
        for (int mrow = wq; mrow < 64; mrow += 8) {
            char* dst = (char*)(base + (size_t)(m0 + mrow) * HID);
#pragma unroll
            for (int k = 0; k < 4; k++) {
                int d = l + 32 * k;
                *(__half*)(dst + pb[k]) = __float2half_rn(sT[d * 66 + mrow] + bv[k]);
            }
        }
    }
}

// ---------------- head-fold output weight -> fp16 pairs [o][c2] ----------------
__global__ void weff_kernel(const float* __restrict__ w0, const float* __restrict__ w1) {
    int k2 = blockIdx.x;
    int s = blockIdx.y;
    int o = threadIdx.x;
    const float* w = (s == 0 ? w0 : w1);
    float e = 0.f, d = 0.f;
#pragma unroll
    for (int h = 0; h < 4; h++) {
        e += w[(size_t)(2 * k2 + HID * h) * C_IN + o];
        d += w[(size_t)(2 * k2 + 1 + HID * h) * C_IN + o];
    }
    g_w2[s][o][k2] = packh(e, d);
}

// =======================================================================
// attention + fused output projection. 8 warps x 16 queries, 16-key
// softmax groups; S-phase uses SPLIT accumulator chains (4 chains/warp)
// to cover HMMA latency. LDS.64 paired B fragments.
// =======================================================================
__global__ void __launch_bounds__(256, 1) attn_kernel(
        const float* __restrict__ x0, const float* __restrict__ x1,
        const float* __restrict__ ob0, const float* __restrict__ ob1,
        float* __restrict__ out) {
    extern __shared__ char sc[];   // [2][65536]: kf at +0, vf at +32768 per buffer

    int tid = threadIdx.x;
    int l = tid & 31, w = tid >> 5;
    int g = l >> 2, j = l & 3;
    int m0 = blockIdx.x * 128;
    int b = blockIdx.y, s = blockIdx.z;
    const __half* Qh = &g_qh[1 - s][b][0][0];
    const __half* Kh = &g_kh[s][b][0][0];
    const __half* Vh = &g_vh[s][b][0][0];
    const float* x = (s == 0 ? x0 : x1) + (size_t)b * C_IN * NTOK;
    const float* ob = (s == 0 ? ob0 : ob1);
    float* oo = out + ((size_t)s * NB + b) * C_IN * NTOK;

    // ---- cp.async prefetch tile 0 (chunk swizzle: ch ^ ((row&7)<<1)) ----
    uint32_t sb = smem_u32(sc);
    int nb0 = tid >> 4;
    int cidx = tid & 15;
    uint32_t kdst = (uint32_t)nb0 * 256 + (uint32_t)((cidx ^ ((nb0 & 7) << 1)) << 4);
    uint32_t vdst = 32768u + kdst;
    const char* ksrc = (const char*)Kh + (size_t)nb0 * 256 + cidx * 16;
    const char* vsrc = (const char*)Vh + (size_t)nb0 * NTOK * 2 + cidx * 16;
#pragma unroll
    for (int u = 0; u < 8; u++) {
        CP16(sb + kdst + u * 4096, ksrc + (size_t)u * 16 * 256);
        CP16(sb + vdst + u * 4096, vsrc + (size_t)u * 16 * NTOK * 2);
    }
    CP_COMMIT();

    // ---- Q fragments -> registers (permuted rows: word = 8ks + 2j + h) ----
    int q0 = m0 + 16 * w;
    uint32_t aq[8][4];
    {
        const uint32_t* p0 = (const uint32_t*)(Qh + (size_t)(q0 + g) * HID);
        const uint32_t* p1 = (const uint32_t*)(Qh + (size_t)(q0 + 8 + g) * HID);
#pragma unroll
        for (int ks = 0; ks < 8; ks++) {
            aq[ks][0] = p0[8 * ks + 2 * j];
            aq[ks][1] = p1[8 * ks + 2 * j];
            aq[ks][2] = p0[8 * ks + 2 * j + 1];
            aq[ks][3] = p1[8 * ks + 2 * j + 1];
        }
    }

    float oacc[16][4] = {};
    float psum0 = 0.f, psum1 = 0.f;
    int goff = (w >> 2) * 4;          // phase-stagger: warps 4-7 start at group 4
    uint32_t swz = (uint32_t)(4 * g); // granule XOR for this lane's rows (row&7 == g)

    for (int t = 0; t < 18; t++) {
        const char* cb = sc + (size_t)(t & 1) * 65536;
        if (t + 1 < 18) {
            uint32_t nbuf = sb + (uint32_t)((t + 1) & 1) * 65536;
            const char* ks2 = ksrc + (size_t)(t + 1) * 128 * 256;
            const char* vs2 = vsrc + (size_t)(t + 1) * 256;
#pragma unroll
            for (int u = 0; u < 8; u++) {
                CP16(nbuf + kdst + u * 4096, ks2 + (size_t)u * 16 * 256);
                CP16(nbuf + vdst + u * 4096, vs2 + (size_t)u * 16 * NTOK * 2);
            }
            CP_COMMIT();
            CP_WAIT1();
        } else {
            const char* wsrc = (const char*)&g_w2[s][0][0];
#pragma unroll
            for (int u = 0; u < 16; u++) {
                int idx = tid + 256 * u;
                int row = idx >> 4, ch = idx & 15;
                CP16(sb + (uint32_t)row * 256 + (uint32_t)((ch ^ (row & 7)) << 4),
                     wsrc + (size_t)idx * 16);
            }
            CP_COMMIT();
            CP_WAIT1();
        }
        __syncthreads();

        const char* kf = cb;
        const char* vf = cb + 32768;

        // ---- 8 staggered groups of 16 keys: S-mma (split chains) -> exp -> PV ----
#pragma unroll
        for (int ntg0 = 0; ntg0 < 8; ntg0++) {
            int ntg = (ntg0 + goff) & 7;
            float s0a[4] = {}, s0b[4] = {}, s1a[4] = {}, s1b[4] = {};
            const char* kr0 = kf + (16 * ntg + g) * 256;
            const char* kr1 = kr0 + 8 * 256;
#pragma unroll
            for (int ks = 0; ks < 4; ks++) {
                uint32_t ea = ((uint32_t)(4 * ks + j) ^ swz) << 3;
                uint32_t eb = ((uint32_t)(4 * (ks + 4) + j) ^ swz) << 3;
                uint2 k0a = *(const uint2*)(kr0 + ea);
                uint2 k1a = *(const uint2*)(kr1 + ea);
                uint2 k0b = *(const uint2*)(kr0 + eb);
                uint2 k1b = *(const uint2*)(kr1 + eb);
                mma16(s0a, aq[ks], k0a.x, k0a.y);
                mma16(s1a, aq[ks], k1a.x, k1a.y);
                mma16(s0b, aq[ks + 4], k0b.x, k0b.y);
                mma16(s1b, aq[ks + 4], k1b.x, k1b.y);
            }
            float a0 = ex2f(s0a[0] + s0b[0]), a1 = ex2f(s0a[1] + s0b[1]);
            float a2 = ex2f(s0a[2] + s0b[2]), a3 = ex2f(s0a[3] + s0b[3]);
            float a4 = ex2f(s1a[0] + s1b[0]), a5 = ex2f(s1a[1] + s1b[1]);
            float a6 = ex2f(s1a[2] + s1b[2]), a7 = ex2f(s1a[3] + s1b[3]);
            psum0 += a0 + a1 + a4 + a5;
            psum1 += a2 + a3 + a6 + a7;
            uint32_t ap[4];
            ap[0] = packh(a0, a1);
            ap[1] = packh(a2, a3);
            ap[2] = packh(a4, a5);
            ap[3] = packh(a6, a7);

            uint32_t ev = ((uint32_t)(4 * ntg + j) ^ swz) << 3;
#pragma unroll
            for (int dt = 0; dt < 16; dt++) {
                uint2 vv = *(const uint2*)(vf + (8 * dt + g) * 256 + ev);
                mma16(oacc[dt], ap, vv.x, vv.y);
            }
        }
        __syncthreads();
    }

    // ---- W_eff arrived ----
    CP_WAIT0();
    __syncthreads();

    // ---- row-sum reduce + pack O into out-GEMM B fragments ----
    psum0 += __shfl_xor_sync(0xffffffffu, psum0, 1);
    psum0 += __shfl_xor_sync(0xffffffffu, psum0, 2);
    psum1 += __shfl_xor_sync(0xffffffffu, psum1, 1);
    psum1 += __shfl_xor_sync(0xffffffffu, psum1, 2);
    float inv0 = 1.f / psum0, inv1 = 1.f / psum1;

    uint32_t bp0[8][2], bp1[8][2];
#pragma unroll
    for (int kk = 0; kk < 8; kk++) {
        bp0[kk][0] = packh(oacc[2 * kk][0] * inv0,     oacc[2 * kk][1] * inv0);
        bp0[kk][1] = packh(oacc[2 * kk + 1][0] * inv0, oacc[2 * kk + 1][1] * inv0);
        bp1[kk][0] = packh(oacc[2 * kk][2] * inv1,     oacc[2 * kk][3] * inv1);
        bp1[kk][1] = packh(oacc[2 * kk + 1][2] * inv1, oacc[2 * kk + 1][3] * inv1);
    }

    // ---- Out[o][m] = Weff H + bias + x : A = Weff (SMEM), B = bp (regs) ----
    const uint32_t* w32 = (const uint32_t*)sc;
#pragma unroll
    for (int ot = 0; ot < 16; ot++) {
        float ac0[4] = {}, ac1[4] = {};
        int r0 = (16 * ot + g) * 64, r1 = (16 * ot + 8 + g) * 64;
#pragma unroll
        for (int kk = 0; kk < 8; kk++) {
            uint32_t a[4];
            int e0 = (8 * kk + j) ^ (4 * g);
            int e1 = (8 * kk + 4 + j) ^ (4 * g);
            a[0] = w32[r0 + e0];
            a[1] = w32[r1 + e0];
            a[2] = w32[r0 + e1];
            a[3] = w32[r1 + e1];
            mma16(ac0, a, bp0[kk][0], bp0[kk][1]);
            mma16(ac1, a, bp1[kk][0], bp1[kk][1]);
        }
        int oa = 16 * ot + g, obr = oa + 8;
        float ba = ob[oa], bb = ob[obr];
        int mA = q0 + 2 * j;
        const float* xr0 = x + (size_t)oa * NTOK + mA;
        const float* xr1 = x + (size_t)obr * NTOK + mA;
        float* or0 = oo + (size_t)oa * NTOK + mA;
        float* or1 = oo + (size_t)obr * NTOK + mA;
        float2 xv;
        xv = *(const float2*)xr0;
        *(float2*)or0 = make_float2(ac0[0] + ba + xv.x, ac0[1] + ba + xv.y);
        xv = *(const float2*)(xr0 + 8);
        *(float2*)(or0 + 8) = make_float2(ac1[0] + ba + xv.x, ac1[1] + ba + xv.y);
        xv = *(const float2*)xr1;
        *(float2*)or1 = make_float2(ac0[2] + bb + xv.x, ac0[3] + bb + xv.y);
        xv = *(const float2*)(xr1 + 8);
        *(float2*)(or1 + 8) = make_float2(ac1[2] + bb + xv.x, ac1[3] + bb + xv.y);
    }
}

// ---------------- launch ----------------
extern "C" void kernel_launch(void* const* d_in, const int* in_sizes, int n_in,
                              void* d_out, int out_size) {
    const float* x0  = (const float*)d_in[0];
    const float* x1  = (const float*)d_in[1];
    const float* ew0 = (const float*)d_in[2];
    const float* eb0 = (const float*)d_in[3];
    const float* ew1 = (const float*)d_in[4];
    const float* eb1 = (const float*)d_in[5];
    const float* ow0 = (const float*)d_in[6];
    const float* ob0 = (const float*)d_in[7];
    const float* ow1 = (const float*)d_in[8];
    const float* ob1 = (const float*)d_in[9];
    float* out = (float*)d_out;

    wh_kernel<<<dim3(384, NSTREAMS), 128>>>(ew0, ew1);
    weff_kernel<<<dim3(HID / 2, NSTREAMS), C_IN>>>(ow0, ow1);

    int smem_e = 9216 + 3 * 16384;   // 58368
    cudaFuncSetAttribute(embed_kernel, cudaFuncAttributeMaxDynamicSharedMemorySize, smem_e);
    embed_kernel<<<dim3(NTOK / 64, 16), 256, smem_e>>>(x0, x1, eb0, eb1);

    int smem_a = 2 * 65536;
    cudaFuncSetAttribute(attn_kernel, cudaFuncAttributeMaxDynamicSharedMemorySize, smem_a);
    attn_kernel<<<dim3(NTOK / 128, NB, NSTREAMS), 256, smem_a>>>(x0, x1, ob0, ob1, out);
}

// round 17
// speedup vs baseline: 1.0125x; 1.0125x over previous
#include <cuda_runtime.h>
#include <cuda_fp16.h>
#include <cstdint>

#define NSTREAMS 2
#define NB 8
#define C_IN 256
#define HID 128
#define NTOK 2304
#define QSCL 0.09016844005f   // 256^-0.5 * log2(e), folded into q (via wh rows o<128)

// ---------------- scratch (device globals; no allocs allowed) ----------------
// g_qh/g_kh rows use a PERMUTED d-order; g_vh rows use the same permutation
// on n within each 128-token block:  val(16k+8h+2j+b) stored at byte 32k+8j+4h+2b.
__device__ __half   g_qh[NSTREAMS][NB][NTOK][HID];
__device__ __half   g_kh[NSTREAMS][NB][NTOK][HID];
__device__ __half   g_vh[NSTREAMS][NB][HID][NTOK];
__device__ uint32_t g_w2[NSTREAMS][C_IN][HID / 2];  // W_eff [o][c2] half2 (c even lo)
__device__ uint32_t g_wh[NSTREAMS][384][C_IN / 2];  // embed W fp16 pairs [o][c2]

// ---------------- helpers ----------------
__device__ __forceinline__ uint32_t packh(float lo, float hi) {
    uint32_t d; asm("cvt.rn.f16x2.f32 %0, %1, %2;" : "=r"(d) : "f"(hi), "f"(lo));
    return d;
}
__device__ __forceinline__ uint32_t h2exp(uint32_t x) {
    uint32_t y; asm("ex2.approx.f16x2 %0, %1;" : "=r"(y) : "r"(x)); return y;
}
__device__ __forceinline__ void mma16(float c[4], const uint32_t a[4],
                                      uint32_t b0, uint32_t b1) {
    asm volatile(
        "mma.sync.aligned.m16n8k16.row.col.f32.f16.f16.f32 "
        "{%0,%1,%2,%3}, {%4,%5,%6,%7}, {%8,%9}, {%0,%1,%2,%3};"
        : "+f"(c[0]), "+f"(c[1]), "+f"(c[2]), "+f"(c[3])
        : "r"(a[0]), "r"(a[1]), "r"(a[2]), "r"(a[3]), "r"(b0), "r"(b1));
}
__device__ __forceinline__ uint32_t smem_u32(const void* p) {
    uint32_t a;
    asm("{ .reg .u64 t; cvta.to.shared.u64 t, %1; cvt.u32.u64 %0, t; }" : "=r"(a) : "l"(p));
    return a;
}
// in-row permutation: value index v (0..127) -> byte offset (0..255)
__device__ __forceinline__ int permb(int v) {
    int ks = v >> 4, r = v & 15;
    return 32 * ks + 8 * ((r >> 1) & 3) + 4 * (r >> 3) + 2 * (v & 1);
}
#define CP16(dst, src) asm volatile("cp.async.cg.shared.global [%0], [%1], 16;" :: "r"(dst), "l"(src))
#define CP_COMMIT()    asm volatile("cp.async.commit_group;" ::: "memory")
#define CP_WAIT1()     asm volatile("cp.async.wait_group 1;" ::: "memory")
#define CP_WAIT0()     asm volatile("cp.async.wait_group 0;" ::: "memory")

// ---------------- pre-convert embed weight to fp16 pairs (QSCL folded for q) ----------------
__global__ void wh_kernel(const float* __restrict__ w0, const float* __restrict__ w1) {
    int o = blockIdx.x;
    int s = blockIdx.y;
    const float* w = (s == 0 ? w0 : w1) + (size_t)o * C_IN;
    float scl = (o < HID) ? QSCL : 1.0f;
    int c2 = threadIdx.x;
    g_wh[s][o][c2] = packh(w[2 * c2] * scl, w[2 * c2 + 1] * scl);
}

// =======================================================================
// embed (fp16 mma): one CTA computes q,k,v for a 64-token m-tile.
// Outputs written in the attn-fragment permuted order (see permb).
// =======================================================================
__global__ void __launch_bounds__(256, 2) embed_kernel(
        const float* __restrict__ x0, const float* __restrict__ x1,
        const float* __restrict__ b0_, const float* __restrict__ b1_) {
    extern __shared__ char esm[];
    uint32_t* sX = (uint32_t*)esm;          // [32 c2][72 pad] half2 words
    char* wsm = esm + 9216;                 // 3 oy x 16384 B, chunk-XOR swizzled
    float* sT = (float*)(esm + 9216);       // [128 d][66 m] transpose overlay

    int z = blockIdx.y;
    int s = z >> 3, b = z & 7;
    const float* x = (s == 0 ? x0 : x1) + (size_t)b * C_IN * NTOK;
    const float* bias = (s == 0 ? b0_ : b1_);
    const uint32_t* wh = &g_wh[s][0][0];
    int m0 = blockIdx.x * 64;
    int tid = threadIdx.x;
    int l = tid & 31, wq = tid >> 5;
    int g = l >> 2, j = l & 3;
    uint32_t sb = smem_u32(esm);

    float acc[3][8][4] = {};

    for (int c = 0; c < 4; c++) {
        int k0 = 64 * c;
#pragma unroll
        for (int u = 0; u < 12; u++) {
            int idx = tid + 256 * u;
            int oyi = idx >> 10, rem = idx & 1023;
            int row = rem >> 3, ch = rem & 7;
            uint32_t dst = sb + 9216u + (uint32_t)oyi * 16384u
                         + (uint32_t)row * 128u + (uint32_t)((ch ^ (row & 7)) << 4);
            const char* src = (const char*)(wh + (size_t)(oyi * 128 + row) * 128
                                            + (k0 >> 1) + ch * 4);
            CP16(dst, src);
        }
        CP_COMMIT();
#pragma unroll
        for (int u = 0; u < 2; u++) {
            int idx = tid + 256 * u;
            int k2 = idx >> 4, m4 = idx & 15;
            const float* xa = x + (size_t)(k0 + 2 * k2) * NTOK + m0 + 4 * m4;
            float4 fa = *(const float4*)xa;
            float4 fb = *(const float4*)(xa + NTOK);
            uint4 p;
            p.x = packh(fa.x, fb.x); p.y = packh(fa.y, fb.y);
            p.z = packh(fa.z, fb.z); p.w = packh(fa.w, fb.w);
            *(uint4*)(sX + k2 * 72 + 4 * m4) = p;
        }
        CP_WAIT0();
        __syncthreads();
#pragma unroll
        for (int oy = 0; oy < 3; oy++) {
            const char* wrow0 = wsm + oy * 16384 + (16 * wq + g) * 128;
            const char* wrow1 = wrow0 + 8 * 128;
#pragma unroll
            for (int ks = 0; ks < 4; ks++) {
                int e0 = ((2 * ks) ^ g) * 16 + 4 * j;
                int e1 = ((2 * ks + 1) ^ g) * 16 + 4 * j;
                uint32_t a[4];
                a[0] = *(const uint32_t*)(wrow0 + e0);
                a[1] = *(const uint32_t*)(wrow1 + e0);
                a[2] = *(const uint32_t*)(wrow0 + e1);
                a[3] = *(const uint32_t*)(wrow1 + e1);
                const uint32_t* xb0 = sX + (8 * ks + j) * 72 + g;
                const uint32_t* xb1 = sX + (8 * ks + 4 + j) * 72 + g;
#pragma unroll
                for (int nt = 0; nt < 8; nt++)
                    mma16(acc[oy][nt], a, xb0[8 * nt], xb1[8 * nt]);
            }
        }
        __syncthreads();
    }

    {   // v epilogue: channel-major rows, PERMUTED n within 128-blocks
        int d0 = 16 * wq + g, d1 = d0 + 8;
        float bv0 = bias[256 + d0], bv1 = bias[256 + d1];
        char* v0 = (char*)&g_vh[s][b][d0][0];
        char* v1 = (char*)&g_vh[s][b][d1][0];
#pragma unroll
        for (int nt = 0; nt < 8; nt++) {
            int m = m0 + 8 * nt + 2 * j;
            int off = (m & ~127) * 2 + permb(m & 127);
            *(__half2*)(v0 + off) = __floats2half2_rn(acc[2][nt][0] + bv0, acc[2][nt][1] + bv0);
            *(__half2*)(v1 + off) = __floats2half2_rn(acc[2][nt][2] + bv1, acc[2][nt][3] + bv1);
        }
    }
#pragma unroll
    for (int oy = 0; oy < 2; oy++) {   // q/k transpose epilogue, PERMUTED d
        __syncthreads();
        int d0 = 16 * wq + g, d1 = d0 + 8;
#pragma unroll
        for (int nt = 0; nt < 8; nt++) {
            int m = 8 * nt + 2 * j;
            *(float2*)(sT + d0 * 66 + m) = make_float2(acc[oy][nt][0], acc[oy][nt][1]);
            *(float2*)(sT + d1 * 66 + m) = make_float2(acc[oy][nt][2], acc[oy][nt][3]);
        }
        __syncthreads();
        float bscl = (oy == 0) ? QSCL : 1.0f;
        __half* base = (oy == 0) ? &g_qh[s][b][0][0] : &g_kh[s][b][0][0];
        float bv[4];
        int pb[4];
#pragma unroll
        for (int k = 0; k < 4; k++) {
            bv[k] = bias[oy * 128 + l + 32 * k] * bscl;
            pb[k] = permb(l + 32 * k);
        }
        for (int mrow = wq; mrow < 64; mrow += 8) {
            char* dst = (char*)(base + (size_t)(m0 + mrow) * HID);
#pragma unroll
            for (int k = 0; k < 4; k++) {
                int d = l + 32 * k;
                *(__half*)(dst + pb[k]) = __float2half_rn(sT[d * 66 + mrow] + bv[k]);
            }
        }
    }
}

// ---------------- head-fold output weight -> fp16 pairs [o][c2] ----------------
__global__ void weff_kernel(const float* __restrict__ w0, const float* __restrict__ w1) {
    int k2 = blockIdx.x;
    int s = blockIdx.y;
    int o = threadIdx.x;
    const float* w = (s == 0 ? w0 : w1);
    float e = 0.f, d = 0.f;
#pragma unroll
    for (int h = 0; h < 4; h++) {
        e += w[(size_t)(2 * k2 + HID * h) * C_IN + o];
        d += w[(size_t)(2 * k2 + 1 + HID * h) * C_IN + o];
    }
    g_w2[s][o][k2] = packh(e, d);
}

// =======================================================================
// attention + fused output projection. 8 warps x 16 queries, 16-key
// softmax groups with warp phase-stagger; LDS.64 paired B fragments.
// Softmax: fp16 logits -> ex2.approx.f16x2 (half the MUFU ops);
// row sums via a ones-column MMA (no FADD chain, no end shuffles).
// =======================================================================
__global__ void __launch_bounds__(256, 1) attn_kernel(
        const float* __restrict__ x0, const float* __restrict__ x1,
        const float* __restrict__ ob0, const float* __restrict__ ob1,
        float* __restrict__ out) {
    extern __shared__ char sc[];   // [2][65536]: kf at +0, vf at +32768 per buffer

    int tid = threadIdx.x;
    int l = tid & 31, w = tid >> 5;
    int g = l >> 2, j = l & 3;
    int m0 = blockIdx.x * 128;
    int b = blockIdx.y, s = blockIdx.z;
    const __half* Qh = &g_qh[1 - s][b][0][0];
    const __half* Kh = &g_kh[s][b][0][0];
    const __half* Vh = &g_vh[s][b][0][0];
    const float* x = (s == 0 ? x0 : x1) + (size_t)b * C_IN * NTOK;
    const float* ob = (s == 0 ? ob0 : ob1);
    float* oo = out + ((size_t)s * NB + b) * C_IN * NTOK;

    // ---- cp.async prefetch tile 0 (chunk swizzle: ch ^ ((row&7)<<1)) ----
    uint32_t sb = smem_u32(sc);
    int nb0 = tid >> 4;
    int cidx = tid & 15;
    uint32_t kdst = (uint32_t)nb0 * 256 + (uint32_t)((cidx ^ ((nb0 & 7) << 1)) << 4);
    uint32_t vdst = 32768u + kdst;
    const char* ksrc = (const char*)Kh + (size_t)nb0 * 256 + cidx * 16;
    const char* vsrc = (const char*)Vh + (size_t)nb0 * NTOK * 2 + cidx * 16;
#pragma unroll
    for (int u = 0; u < 8; u++) {
        CP16(sb + kdst + u * 4096, ksrc + (size_t)u * 16 * 256);
        CP16(sb + vdst + u * 4096, vsrc + (size_t)u * 16 * NTOK * 2);
    }
    CP_COMMIT();

    // ---- Q fragments -> registers (permuted rows: word = 8ks + 2j + h) ----
    int q0 = m0 + 16 * w;
    uint32_t aq[8][4];
    {
        const uint32_t* p0 = (const uint32_t*)(Qh + (size_t)(q0 + g) * HID);
        const uint32_t* p1 = (const uint32_t*)(Qh + (size_t)(q0 + 8 + g) * HID);
#pragma unroll
        for (int ks = 0; ks < 8; ks++) {
            aq[ks][0] = p0[8 * ks + 2 * j];
            aq[ks][1] = p1[8 * ks + 2 * j];
            aq[ks][2] = p0[8 * ks + 2 * j + 1];
            aq[ks][3] = p1[8 * ks + 2 * j + 1];
        }
    }

    float oacc[16][4] = {};
    float psacc[4] = {};              // ones-column row sums (c0/c1: row g, c2/c3: row g+8)
    const uint32_t ONES = 0x3C003C00u;
    int goff = (w >> 2) * 4;          // phase-stagger: warps 4-7 start at group 4
    uint32_t swz = (uint32_t)(4 * g); // granule XOR for this lane's rows (row&7 == g)

    for (int t = 0; t < 18; t++) {
        const char* cb = sc + (size_t)(t & 1) * 65536;
        if (t + 1 < 18) {
            uint32_t nbuf = sb + (uint32_t)((t + 1) & 1) * 65536;
            const char* ks2 = ksrc + (size_t)(t + 1) * 128 * 256;
            const char* vs2 = vsrc + (size_t)(t + 1) * 256;
#pragma unroll
            for (int u = 0; u < 8; u++) {
                CP16(nbuf + kdst + u * 4096, ks2 + (size_t)u * 16 * 256);
                CP16(nbuf + vdst + u * 4096, vs2 + (size_t)u * 16 * NTOK * 2);
            }
            CP_COMMIT();
            CP_WAIT1();
        } else {
            const char* wsrc = (const char*)&g_w2[s][0][0];
#pragma unroll
            for (int u = 0; u < 16; u++) {
                int idx = tid + 256 * u;
                int row = idx >> 4, ch = idx & 15;
                CP16(sb + (uint32_t)row * 256 + (uint32_t)((ch ^ (row & 7)) << 4),
                     wsrc + (size_t)idx * 16);
            }
            CP_COMMIT();
            CP_WAIT1();
        }
        __syncthreads();

        const char* kf = cb;
        const char* vf = cb + 32768;

        // ---- 8 staggered groups of 16 keys: S-mma -> f16x2 exp -> PV-mma ----
#pragma unroll
        for (int ntg0 = 0; ntg0 < 8; ntg0++) {
            int ntg = (ntg0 + goff) & 7;
            float s0[4] = {}, s1[4] = {};
            const char* kr0 = kf + (16 * ntg + g) * 256;
            const char* kr1 = kr0 + 8 * 256;
#pragma unroll
            for (int ks = 0; ks < 8; ks++) {
                uint32_t e = ((uint32_t)(4 * ks + j) ^ swz) << 3;
                uint2 k0v = *(const uint2*)(kr0 + e);
                uint2 k1v = *(const uint2*)(kr1 + e);
                mma16(s0, aq[ks], k0v.x, k0v.y);
                mma16(s1, aq[ks], k1v.x, k1v.y);
            }
            // pack fp16 logits, exp2 on packed pairs
            uint32_t ap[4];
            ap[0] = h2exp(packh(s0[0], s0[1]));
            ap[1] = h2exp(packh(s0[2], s0[3]));
            ap[2] = h2exp(packh(s1[0], s1[1]));
            ap[3] = h2exp(packh(s1[2], s1[3]));

            // row sums via ones-column mma (independent chain, issued first)
            mma16(psacc, ap, ONES, ONES);

            uint32_t ev = ((uint32_t)(4 * ntg + j) ^ swz) << 3;
#pragma unroll
            for (int dt = 0; dt < 16; dt++) {
                uint2 vv = *(const uint2*)(vf + (8 * dt + g) * 256 + ev);
                mma16(oacc[dt], ap, vv.x, vv.y);
            }
        }
        __syncthreads();
    }

    // ---- W_eff arrived ----
    CP_WAIT0();
    __syncthreads();

    // ---- normalize + pack O into out-GEMM B fragments (no shuffles needed) ----
    float inv0 = 1.f / psacc[0], inv1 = 1.f / psacc[2];

    uint32_t bp0[8][2], bp1[8][2];
#pragma unroll
    for (int kk = 0; kk < 8; kk++) {
        bp0[kk][0] = packh(oacc[2 * kk][0] * inv0,     oacc[2 * kk][1] * inv0);
        bp0[kk][1] = packh(oacc[2 * kk + 1][0] * inv0, oacc[2 * kk + 1][1] * inv0);
        bp1[kk][0] = packh(oacc[2 * kk][2] * inv1,     oacc[2 * kk][3] * inv1);
        bp1[kk][1] = packh(oacc[2 * kk + 1][2] * inv1, oacc[2 * kk + 1][3] * inv1);
    }

    // ---- Out[o][m] = Weff H + bias + x : A = Weff (SMEM), B = bp (regs) ----
    const uint32_t* w32 = (const uint32_t*)sc;
#pragma unroll
    for (int ot = 0; ot < 16; ot++) {
        float ac0[4] = {}, ac1[4] = {};
        int r0 = (16 * ot + g) * 64, r1 = (16 * ot + 8 + g) * 64;
#pragma unroll
        for (int kk = 0; kk < 8; kk++) {
            uint32_t a[4];
            int e0 = (8 * kk + j) ^ (4 * g);
            int e1 = (8 * kk + 4 + j) ^ (4 * g);
            a[0] = w32[r0 + e0];
            a[1] = w32[r1 + e0];
            a[2] = w32[r0 + e1];
            a[3] = w32[r1 + e1];
            mma16(ac0, a, bp0[kk][0], bp0[kk][1]);
            mma16(ac1, a, bp1[kk][0], bp1[kk][1]);
        }
        int oa = 16 * ot + g, obr = oa + 8;
        float ba = ob[oa], bb = ob[obr];
        int mA = q0 + 2 * j;
        const float* xr0 = x + (size_t)oa * NTOK + mA;
        const float* xr1 = x + (size_t)obr * NTOK + mA;
        float* or0 = oo + (size_t)oa * NTOK + mA;
        float* or1 = oo + (size_t)obr * NTOK + mA;
        float2 xv;
        xv = *(const float2*)xr0;
        *(float2*)or0 = make_float2(ac0[0] + ba + xv.x, ac0[1] + ba + xv.y);
        xv = *(const float2*)(xr0 + 8);
        *(float2*)(or0 + 8) = make_float2(ac1[0] + ba + xv.x, ac1[1] + ba + xv.y);
        xv = *(const float2*)xr1;
        *(float2*)or1 = make_float2(ac0[2] + bb + xv.x, ac0[3] + bb + xv.y);
        xv = *(const float2*)(xr1 + 8);
        *(float2*)(or1 + 8) = make_float2(ac1[2] + bb + xv.x, ac1[3] + bb + xv.y);
    }
}

// ---------------- launch ----------------
extern "C" void kernel_launch(void* const* d_in, const int* in_sizes, int n_in,
                              void* d_out, int out_size) {
    const float* x0  = (const float*)d_in[0];
    const float* x1  = (const float*)d_in[1];
    const float* ew0 = (const float*)d_in[2];
    const float* eb0 = (const float*)d_in[3];
    const float* ew1 = (const float*)d_in[4];
    const float* eb1 = (const float*)d_in[5];
    const float* ow0 = (const float*)d_in[6];
    const float* ob0 = (const float*)d_in[7];
    const float* ow1 = (const float*)d_in[8];
    const float* ob1 = (const float*)d_in[9];
    float* out = (float*)d_out;

    wh_kernel<<<dim3(384, NSTREAMS), 128>>>(ew0, ew1);
    weff_kernel<<<dim3(HID / 2, NSTREAMS), C_IN>>>(ow0, ow1);

    int smem_e = 9216 + 3 * 16384;   // 58368
    cudaFuncSetAttribute(embed_kernel, cudaFuncAttributeMaxDynamicSharedMemorySize, smem_e);
    embed_kernel<<<dim3(NTOK / 64, 16), 256, smem_e>>>(x0, x1, eb0, eb1);

    int smem_a = 2 * 65536;
    cudaFuncSetAttribute(attn_kernel, cudaFuncAttributeMaxDynamicSharedMemorySize, smem_a);
    attn_kernel<<<dim3(NTOK / 128, NB, NSTREAMS), 256, smem_a>>>(x0, x1, ob0, ob1, out);
}